// round 2
// baseline (speedup 1.0000x reference)
#include <cuda_runtime.h>
#include <cstdint>

#define N_GAUSS 8192
#define GH 160
#define GW 160
#define GD 16
#define VOX 0.4f
#define VMINX (-32.0f)
#define VMINY (-32.0f)
#define VMINZ (-1.0f)

// Precomputed per-gaussian data: 4 x float4 each
//  [0] mu.x, mu.y, mu.z, opacity
//  [1] 3sx, 3sy, 3sz, cinv00
//  [2] cinv11, cinv22, cinv01, cinv02
//  [3] cinv12, -, -, -
__device__ float4 g_prec[N_GAUSS * 4];
// Packed integer voxel AABB: x = xmin|xmax<<8|ymin<<16|ymax<<24, y = zmin|zmax<<8
__device__ uint2 g_aabb[N_GAUSS];

__global__ void precompute_kernel(const float* __restrict__ means,
                                  const float* __restrict__ opac,
                                  const float* __restrict__ scales,
                                  const float* __restrict__ rots) {
    int i = blockIdx.x * blockDim.x + threadIdx.x;
    if (i >= N_GAUSS) return;

    float qw = rots[4*i+0], qx = rots[4*i+1], qy = rots[4*i+2], qz = rots[4*i+3];
    float invn = rsqrtf(qw*qw + qx*qx + qy*qy + qz*qz);
    qw *= invn; qx *= invn; qy *= invn; qz *= invn;

    float r00 = 1.f - 2.f*(qy*qy + qz*qz), r01 = 2.f*(qx*qy - qw*qz), r02 = 2.f*(qx*qz + qw*qy);
    float r10 = 2.f*(qx*qy + qw*qz), r11 = 1.f - 2.f*(qx*qx + qz*qz), r12 = 2.f*(qy*qz - qw*qx);
    float r20 = 2.f*(qx*qz - qw*qy), r21 = 2.f*(qy*qz + qw*qx), r22 = 1.f - 2.f*(qx*qx + qy*qy);

    float sx = scales[3*i+0], sy = scales[3*i+1], sz = scales[3*i+2];
    float ax = sx*sx, ay = sy*sy, az = sz*sz;
    float vx = 1.f/ax, vy = 1.f/ay, vz = 1.f/az;

    // 3*sigma (sigma = sqrt(diag(R S^2 R^T)))
    float s3x = 3.f * sqrtf(r00*r00*ax + r01*r01*ay + r02*r02*az);
    float s3y = 3.f * sqrtf(r10*r10*ax + r11*r11*ay + r12*r12*az);
    float s3z = 3.f * sqrtf(r20*r20*ax + r21*r21*ay + r22*r22*az);

    // cov_inv = R diag(1/s^2) R^T (symmetric)
    float c00 = r00*r00*vx + r01*r01*vy + r02*r02*vz;
    float c11 = r10*r10*vx + r11*r11*vy + r12*r12*vz;
    float c22 = r20*r20*vx + r21*r21*vy + r22*r22*vz;
    float c01 = r00*r10*vx + r01*r11*vy + r02*r12*vz;
    float c02 = r00*r20*vx + r01*r21*vy + r02*r22*vz;
    float c12 = r10*r20*vx + r11*r21*vy + r12*r22*vz;

    float mx = means[3*i+0], my = means[3*i+1], mz = means[3*i+2];

    g_prec[4*i+0] = make_float4(mx, my, mz, opac[i]);
    g_prec[4*i+1] = make_float4(s3x, s3y, s3z, c00);
    g_prec[4*i+2] = make_float4(c11, c22, c01, c02);
    g_prec[4*i+3] = make_float4(c12, 0.f, 0.f, 0.f);

    // Conservative integer voxel AABB (widened by 1 voxel each side).
    // Voxel center: (idx + 0.5) * VOX + VMIN. Inverse: idx = (c - VMIN)/VOX - 0.5
    int x0 = (int)floorf((mx - s3x - VMINX) * 2.5f - 0.5f) - 1;
    int x1 = (int)floorf((mx + s3x - VMINX) * 2.5f - 0.5f) + 2;
    int y0 = (int)floorf((my - s3y - VMINY) * 2.5f - 0.5f) - 1;
    int y1 = (int)floorf((my + s3y - VMINY) * 2.5f - 0.5f) + 2;
    int z0 = (int)floorf((mz - s3z - VMINZ) * 2.5f - 0.5f) - 1;
    int z1 = (int)floorf((mz + s3z - VMINZ) * 2.5f - 0.5f) + 2;
    x0 = min(max(x0, 0), GH - 1); x1 = min(max(x1, 0), GH - 1);
    y0 = min(max(y0, 0), GW - 1); y1 = min(max(y1, 0), GW - 1);
    z0 = min(max(z0, 0), GD - 1); z1 = min(max(z1, 0), GD - 1);

    uint2 p;
    p.x = (unsigned)x0 | ((unsigned)x1 << 8) | ((unsigned)y0 << 16) | ((unsigned)y1 << 24);
    p.y = (unsigned)z0 | ((unsigned)z1 << 8);
    g_aabb[i] = p;
}

__global__ void __launch_bounds__(256) splat_kernel(const float* __restrict__ feats,
                                                    float* __restrict__ out) {
    __shared__ unsigned short slist[N_GAUSS];
    __shared__ int swarp[9];

    const int tid = threadIdx.x;
    const int tx0 = blockIdx.x * 16;
    const int ty0 = blockIdx.y * 16;
    const int tz  = blockIdx.z;
    const int lane = tid & 31, wid = tid >> 5;

    // ---- Cull: each thread tests a contiguous chunk of 32 gaussians ----
    const int base = tid * 32;
    int cnt = 0;
    #pragma unroll 8
    for (int k = 0; k < 32; k++) {
        uint2 p = g_aabb[base + k];
        int xmin = p.x & 255, xmax = (p.x >> 8) & 255;
        int ymin = (p.x >> 16) & 255, ymax = (p.x >> 24) & 255;
        int zmin = p.y & 255, zmax = (p.y >> 8) & 255;
        bool hit = (xmin <= tx0 + 15) & (xmax >= tx0) &
                   (ymin <= ty0 + 15) & (ymax >= ty0) &
                   (zmin <= tz) & (zmax >= tz);
        cnt += hit ? 1 : 0;
    }

    // Warp-level inclusive scan of counts, then block combine (deterministic order).
    int inc = cnt;
    #pragma unroll
    for (int o = 1; o < 32; o <<= 1) {
        int y = __shfl_up_sync(0xffffffffu, inc, o);
        if (lane >= o) inc += y;
    }
    if (lane == 31) swarp[wid] = inc;
    __syncthreads();
    if (tid == 0) {
        int s = 0;
        #pragma unroll
        for (int w2 = 0; w2 < 8; w2++) { int t = swarp[w2]; swarp[w2] = s; s += t; }
        swarp[8] = s;
    }
    __syncthreads();
    int off = swarp[wid] + (inc - cnt);   // exclusive prefix for this thread

    #pragma unroll 8
    for (int k = 0; k < 32; k++) {
        uint2 p = g_aabb[base + k];
        int xmin = p.x & 255, xmax = (p.x >> 8) & 255;
        int ymin = (p.x >> 16) & 255, ymax = (p.x >> 24) & 255;
        int zmin = p.y & 255, zmax = (p.y >> 8) & 255;
        bool hit = (xmin <= tx0 + 15) & (xmax >= tx0) &
                   (ymin <= ty0 + 15) & (ymax >= ty0) &
                   (zmin <= tz) & (zmax >= tz);
        if (hit) slist[off++] = (unsigned short)(base + k);
    }
    __syncthreads();
    const int nsurv = swarp[8];

    // ---- Evaluate: one voxel per thread ----
    const int iy = tid & 15;
    const int ix = tid >> 4;
    const float cx = ((float)(tx0 + ix) + 0.5f) * VOX + VMINX;
    const float cy = ((float)(ty0 + iy) + 0.5f) * VOX + VMINY;
    const float cz = ((float)tz + 0.5f) * VOX + VMINZ;

    float acc[32];
    #pragma unroll
    for (int k = 0; k < 32; k++) acc[k] = 0.f;

    for (int j = 0; j < nsurv; j++) {
        const int gi = slist[j];
        float4 f0 = g_prec[4*gi + 0];
        float4 f1 = g_prec[4*gi + 1];
        float dx = cx - f0.x, dy = cy - f0.y, dz = cz - f0.z;
        bool m = (fabsf(dx) <= f1.x) & (fabsf(dy) <= f1.y) & (fabsf(dz) <= f1.z);
        if (__ballot_sync(0xffffffffu, m)) {
            float wgt = 0.f;
            if (m) {
                float4 f2 = g_prec[4*gi + 2];
                float4 f3 = g_prec[4*gi + 3];
                float maha = f1.w * dx * dx + f2.x * dy * dy + f2.y * dz * dz
                           + 2.f * (f2.z * dx * dy + f2.w * dx * dz + f3.x * dy * dz);
                wgt = f0.w * __expf(-0.5f * maha);
            }
            const float4* fp = (const float4*)(feats + (size_t)gi * 32);
            #pragma unroll
            for (int k = 0; k < 8; k++) {
                float4 f = __ldg(fp + k);
                acc[4*k+0] += wgt * f.x;
                acc[4*k+1] += wgt * f.y;
                acc[4*k+2] += wgt * f.z;
                acc[4*k+3] += wgt * f.w;
            }
        }
    }

    size_t o = ((((size_t)(tx0 + ix)) * GW + (size_t)(ty0 + iy)) * GD + (size_t)tz) * 32;
    float4* op = (float4*)(out + o);
    #pragma unroll
    for (int k = 0; k < 8; k++)
        op[k] = make_float4(acc[4*k+0], acc[4*k+1], acc[4*k+2], acc[4*k+3]);
}

extern "C" void kernel_launch(void* const* d_in, const int* in_sizes, int n_in,
                              void* d_out, int out_size) {
    const float* means  = (const float*)d_in[0];
    const float* opac   = (const float*)d_in[1];
    const float* scales = (const float*)d_in[2];
    const float* rots   = (const float*)d_in[3];
    const float* feats  = (const float*)d_in[4];
    float* out = (float*)d_out;

    precompute_kernel<<<(N_GAUSS + 255) / 256, 256>>>(means, opac, scales, rots);
    splat_kernel<<<dim3(GH / 16, GW / 16, GD), 256>>>(feats, out);
}

// round 3
// speedup vs baseline: 1.4619x; 1.4619x over previous
#include <cuda_runtime.h>
#include <cstdint>

#define N_GAUSS 8192
#define GH 160
#define GW 160
#define GD 16
#define VOX 0.4f
#define VMINX (-32.0f)
#define VMINY (-32.0f)
#define VMINZ (-1.0f)

// Precomputed per-gaussian data: 4 x float4 each
//  [0] mu.x, mu.y, mu.z, opacity
//  [1] 3sx, 3sy, 3sz, cinv00
//  [2] cinv11, cinv22, cinv01, cinv02
//  [3] cinv12, -, -, -
__device__ float4 g_prec[N_GAUSS * 4];
// Packed integer voxel AABB: x = xmin|xmax<<8|ymin<<16|ymax<<24, y = zmin|zmax<<8
__device__ uint2 g_aabb[N_GAUSS];

__global__ void precompute_kernel(const float* __restrict__ means,
                                  const float* __restrict__ opac,
                                  const float* __restrict__ scales,
                                  const float* __restrict__ rots) {
    int i = blockIdx.x * blockDim.x + threadIdx.x;
    if (i >= N_GAUSS) return;

    float qw = rots[4*i+0], qx = rots[4*i+1], qy = rots[4*i+2], qz = rots[4*i+3];
    float invn = rsqrtf(qw*qw + qx*qx + qy*qy + qz*qz);
    qw *= invn; qx *= invn; qy *= invn; qz *= invn;

    float r00 = 1.f - 2.f*(qy*qy + qz*qz), r01 = 2.f*(qx*qy - qw*qz), r02 = 2.f*(qx*qz + qw*qy);
    float r10 = 2.f*(qx*qy + qw*qz), r11 = 1.f - 2.f*(qx*qx + qz*qz), r12 = 2.f*(qy*qz - qw*qx);
    float r20 = 2.f*(qx*qz - qw*qy), r21 = 2.f*(qy*qz + qw*qx), r22 = 1.f - 2.f*(qx*qx + qy*qy);

    float sx = scales[3*i+0], sy = scales[3*i+1], sz = scales[3*i+2];
    float ax = sx*sx, ay = sy*sy, az = sz*sz;
    float vx = 1.f/ax, vy = 1.f/ay, vz = 1.f/az;

    float s3x = 3.f * sqrtf(r00*r00*ax + r01*r01*ay + r02*r02*az);
    float s3y = 3.f * sqrtf(r10*r10*ax + r11*r11*ay + r12*r12*az);
    float s3z = 3.f * sqrtf(r20*r20*ax + r21*r21*ay + r22*r22*az);

    float c00 = r00*r00*vx + r01*r01*vy + r02*r02*vz;
    float c11 = r10*r10*vx + r11*r11*vy + r12*r12*vz;
    float c22 = r20*r20*vx + r21*r21*vy + r22*r22*vz;
    float c01 = r00*r10*vx + r01*r11*vy + r02*r12*vz;
    float c02 = r00*r20*vx + r01*r21*vy + r02*r22*vz;
    float c12 = r10*r20*vx + r11*r21*vy + r12*r22*vz;

    float mx = means[3*i+0], my = means[3*i+1], mz = means[3*i+2];

    g_prec[4*i+0] = make_float4(mx, my, mz, opac[i]);
    g_prec[4*i+1] = make_float4(s3x, s3y, s3z, c00);
    g_prec[4*i+2] = make_float4(c11, c22, c01, c02);
    g_prec[4*i+3] = make_float4(c12, 0.f, 0.f, 0.f);

    // Conservative integer voxel AABB (widened by 1 voxel each side).
    int x0 = (int)floorf((mx - s3x - VMINX) * 2.5f - 0.5f) - 1;
    int x1 = (int)floorf((mx + s3x - VMINX) * 2.5f - 0.5f) + 2;
    int y0 = (int)floorf((my - s3y - VMINY) * 2.5f - 0.5f) - 1;
    int y1 = (int)floorf((my + s3y - VMINY) * 2.5f - 0.5f) + 2;
    int z0 = (int)floorf((mz - s3z - VMINZ) * 2.5f - 0.5f) - 1;
    int z1 = (int)floorf((mz + s3z - VMINZ) * 2.5f - 0.5f) + 2;
    x0 = min(max(x0, 0), GH - 1); x1 = min(max(x1, 0), GH - 1);
    y0 = min(max(y0, 0), GW - 1); y1 = min(max(y1, 0), GW - 1);
    z0 = min(max(z0, 0), GD - 1); z1 = min(max(z1, 0), GD - 1);

    uint2 p;
    p.x = (unsigned)x0 | ((unsigned)x1 << 8) | ((unsigned)y0 << 16) | ((unsigned)y1 << 24);
    p.y = (unsigned)z0 | ((unsigned)z1 << 8);
    g_aabb[i] = p;
}

// Tile = 8x8x8 voxels (512), 256 threads, 2 z-adjacent voxels per thread.
__global__ void __launch_bounds__(256, 2) splat_kernel(const float* __restrict__ feats,
                                                       float* __restrict__ out) {
    __shared__ unsigned short slist[N_GAUSS];
    __shared__ int swarp[9];

    const int tid = threadIdx.x;
    const int tx0 = blockIdx.x * 8;
    const int ty0 = blockIdx.y * 8;
    const int tz0 = blockIdx.z * 8;
    const int lane = tid & 31, wid = tid >> 5;

    // ---- Cull: each thread tests a contiguous chunk of 32 gaussians ----
    const int base = tid * 32;
    int cnt = 0;
    #pragma unroll 8
    for (int k = 0; k < 32; k++) {
        uint2 p = g_aabb[base + k];
        int xmin = p.x & 255, xmax = (p.x >> 8) & 255;
        int ymin = (p.x >> 16) & 255, ymax = (p.x >> 24) & 255;
        int zmin = p.y & 255, zmax = (p.y >> 8) & 255;
        bool hit = (xmin <= tx0 + 7) & (xmax >= tx0) &
                   (ymin <= ty0 + 7) & (ymax >= ty0) &
                   (zmin <= tz0 + 7) & (zmax >= tz0);
        cnt += hit ? 1 : 0;
    }

    int inc = cnt;
    #pragma unroll
    for (int o = 1; o < 32; o <<= 1) {
        int y = __shfl_up_sync(0xffffffffu, inc, o);
        if (lane >= o) inc += y;
    }
    if (lane == 31) swarp[wid] = inc;
    __syncthreads();
    if (tid == 0) {
        int s = 0;
        #pragma unroll
        for (int w2 = 0; w2 < 8; w2++) { int t = swarp[w2]; swarp[w2] = s; s += t; }
        swarp[8] = s;
    }
    __syncthreads();
    int off = swarp[wid] + (inc - cnt);

    #pragma unroll 8
    for (int k = 0; k < 32; k++) {
        uint2 p = g_aabb[base + k];
        int xmin = p.x & 255, xmax = (p.x >> 8) & 255;
        int ymin = (p.x >> 16) & 255, ymax = (p.x >> 24) & 255;
        int zmin = p.y & 255, zmax = (p.y >> 8) & 255;
        bool hit = (xmin <= tx0 + 7) & (xmax >= tx0) &
                   (ymin <= ty0 + 7) & (ymax >= ty0) &
                   (zmin <= tz0 + 7) & (zmax >= tz0);
        if (hit) slist[off++] = (unsigned short)(base + k);
    }
    __syncthreads();
    const int nsurv = swarp[8];

    // ---- Evaluate: two z-adjacent voxels per thread ----
    // Warp covers a 1x8x8 slab: ix = wid, iy = (tid>>2)&7, iz in {2*(tid&3), +1}
    const int izh = (tid & 3) << 1;
    const int iy = (tid >> 2) & 7;
    const int ix = tid >> 5;
    const float cx  = ((float)(tx0 + ix) + 0.5f) * VOX + VMINX;
    const float cy  = ((float)(ty0 + iy) + 0.5f) * VOX + VMINY;
    const float cz0 = ((float)(tz0 + izh) + 0.5f) * VOX + VMINZ;
    const float cz1 = ((float)(tz0 + izh + 1) + 0.5f) * VOX + VMINZ;

    float acc0[32], acc1[32];
    #pragma unroll
    for (int k = 0; k < 32; k++) { acc0[k] = 0.f; acc1[k] = 0.f; }

    for (int j = 0; j < nsurv; j++) {
        const int gi = slist[j];
        float4 f0 = g_prec[4*gi + 0];
        float4 f1 = g_prec[4*gi + 1];
        float dx = cx - f0.x, dy = cy - f0.y;
        float dz0 = cz0 - f0.z, dz1 = cz1 - f0.z;
        bool mxy = (fabsf(dx) <= f1.x) & (fabsf(dy) <= f1.y);
        bool m0 = mxy & (fabsf(dz0) <= f1.z);
        bool m1 = mxy & (fabsf(dz1) <= f1.z);
        if (__ballot_sync(0xffffffffu, m0 | m1)) {
            float wgt0 = 0.f, wgt1 = 0.f;
            if (m0 | m1) {
                float4 f2 = g_prec[4*gi + 2];
                float4 f3 = g_prec[4*gi + 3];
                // shared xy part of mahalanobis
                float txy = f1.w * dx * dx + f2.x * dy * dy + 2.f * f2.z * dx * dy;
                float u   = f2.w * dx + f3.x * dy;           // c02*dx + c12*dy
                if (m0) {
                    float maha0 = txy + f2.y * dz0 * dz0 + 2.f * dz0 * u;
                    wgt0 = f0.w * __expf(-0.5f * maha0);
                }
                if (m1) {
                    float maha1 = txy + f2.y * dz1 * dz1 + 2.f * dz1 * u;
                    wgt1 = f0.w * __expf(-0.5f * maha1);
                }
            }
            const float4* fp = (const float4*)(feats + (size_t)gi * 32);
            #pragma unroll
            for (int k = 0; k < 8; k++) {
                float4 f = __ldg(fp + k);
                acc0[4*k+0] += wgt0 * f.x;
                acc0[4*k+1] += wgt0 * f.y;
                acc0[4*k+2] += wgt0 * f.z;
                acc0[4*k+3] += wgt0 * f.w;
                acc1[4*k+0] += wgt1 * f.x;
                acc1[4*k+1] += wgt1 * f.y;
                acc1[4*k+2] += wgt1 * f.z;
                acc1[4*k+3] += wgt1 * f.w;
            }
        }
    }

    size_t o = ((((size_t)(tx0 + ix)) * GW + (size_t)(ty0 + iy)) * GD + (size_t)(tz0 + izh)) * 32;
    float4* op = (float4*)(out + o);
    #pragma unroll
    for (int k = 0; k < 8; k++)
        op[k] = make_float4(acc0[4*k+0], acc0[4*k+1], acc0[4*k+2], acc0[4*k+3]);
    #pragma unroll
    for (int k = 0; k < 8; k++)
        op[8 + k] = make_float4(acc1[4*k+0], acc1[4*k+1], acc1[4*k+2], acc1[4*k+3]);
}

extern "C" void kernel_launch(void* const* d_in, const int* in_sizes, int n_in,
                              void* d_out, int out_size) {
    const float* means  = (const float*)d_in[0];
    const float* opac   = (const float*)d_in[1];
    const float* scales = (const float*)d_in[2];
    const float* rots   = (const float*)d_in[3];
    const float* feats  = (const float*)d_in[4];
    float* out = (float*)d_out;

    precompute_kernel<<<(N_GAUSS + 255) / 256, 256>>>(means, opac, scales, rots);
    splat_kernel<<<dim3(GH / 8, GW / 8, GD / 8), 256>>>(feats, out);
}

// round 5
// speedup vs baseline: 1.5266x; 1.0442x over previous
#include <cuda_runtime.h>
#include <cstdint>

#define N_GAUSS 8192
#define GH 160
#define GW 160
#define GD 16
#define VOX 0.4f
#define VMINX (-32.0f)
#define VMINY (-32.0f)
#define VMINZ (-1.0f)

// Precomputed per-gaussian data: 4 x float4 each
//  [0] mu.x, mu.y, mu.z, opacity
//  [1] 3sx, 3sy, 3sz, cinv00
//  [2] cinv11, cinv22, cinv01, cinv02
//  [3] cinv12, -, -, -
__device__ float4 g_prec[N_GAUSS * 4];
// Packed integer voxel AABB: x = xmin|xmax<<8|ymin<<16|ymax<<24, y = zmin|zmax<<8
__device__ uint2 g_aabb[N_GAUSS];

__global__ void precompute_kernel(const float* __restrict__ means,
                                  const float* __restrict__ opac,
                                  const float* __restrict__ scales,
                                  const float* __restrict__ rots) {
    int i = blockIdx.x * blockDim.x + threadIdx.x;
    if (i >= N_GAUSS) return;

    float qw = rots[4*i+0], qx = rots[4*i+1], qy = rots[4*i+2], qz = rots[4*i+3];
    float invn = rsqrtf(qw*qw + qx*qx + qy*qy + qz*qz);
    qw *= invn; qx *= invn; qy *= invn; qz *= invn;

    float r00 = 1.f - 2.f*(qy*qy + qz*qz), r01 = 2.f*(qx*qy - qw*qz), r02 = 2.f*(qx*qz + qw*qy);
    float r10 = 2.f*(qx*qy + qw*qz), r11 = 1.f - 2.f*(qx*qx + qz*qz), r12 = 2.f*(qy*qz - qw*qx);
    float r20 = 2.f*(qx*qz - qw*qy), r21 = 2.f*(qy*qz + qw*qx), r22 = 1.f - 2.f*(qx*qx + qy*qy);

    float sx = scales[3*i+0], sy = scales[3*i+1], sz = scales[3*i+2];
    float ax = sx*sx, ay = sy*sy, az = sz*sz;
    float vx = 1.f/ax, vy = 1.f/ay, vz = 1.f/az;

    float s3x = 3.f * sqrtf(r00*r00*ax + r01*r01*ay + r02*r02*az);
    float s3y = 3.f * sqrtf(r10*r10*ax + r11*r11*ay + r12*r12*az);
    float s3z = 3.f * sqrtf(r20*r20*ax + r21*r21*ay + r22*r22*az);

    float c00 = r00*r00*vx + r01*r01*vy + r02*r02*vz;
    float c11 = r10*r10*vx + r11*r11*vy + r12*r12*vz;
    float c22 = r20*r20*vx + r21*r21*vy + r22*r22*vz;
    float c01 = r00*r10*vx + r01*r11*vy + r02*r12*vz;
    float c02 = r00*r20*vx + r01*r21*vy + r02*r22*vz;
    float c12 = r10*r20*vx + r11*r21*vy + r12*r22*vz;

    float mx = means[3*i+0], my = means[3*i+1], mz = means[3*i+2];

    g_prec[4*i+0] = make_float4(mx, my, mz, opac[i]);
    g_prec[4*i+1] = make_float4(s3x, s3y, s3z, c00);
    g_prec[4*i+2] = make_float4(c11, c22, c01, c02);
    g_prec[4*i+3] = make_float4(c12, 0.f, 0.f, 0.f);

    // Conservative integer voxel AABB (widened by 1 voxel each side).
    int x0 = (int)floorf((mx - s3x - VMINX) * 2.5f - 0.5f) - 1;
    int x1 = (int)floorf((mx + s3x - VMINX) * 2.5f - 0.5f) + 2;
    int y0 = (int)floorf((my - s3y - VMINY) * 2.5f - 0.5f) - 1;
    int y1 = (int)floorf((my + s3y - VMINY) * 2.5f - 0.5f) + 2;
    int z0 = (int)floorf((mz - s3z - VMINZ) * 2.5f - 0.5f) - 1;
    int z1 = (int)floorf((mz + s3z - VMINZ) * 2.5f - 0.5f) + 2;
    x0 = min(max(x0, 0), GH - 1); x1 = min(max(x1, 0), GH - 1);
    y0 = min(max(y0, 0), GW - 1); y1 = min(max(y1, 0), GW - 1);
    z0 = min(max(z0, 0), GD - 1); z1 = min(max(z1, 0), GD - 1);

    uint2 p;
    p.x = (unsigned)x0 | ((unsigned)x1 << 8) | ((unsigned)y0 << 16) | ((unsigned)y1 << 24);
    p.y = (unsigned)z0 | ((unsigned)z1 << 8);
    g_aabb[i] = p;
}

// Tile = 8x8x8 voxels (512), 256 threads, 2 z-adjacent voxels per thread.
// Each warp covers a compact 4x4x4 voxel cube (best whole-warp skip rate).
__global__ void __launch_bounds__(256, 2) splat_kernel(const float* __restrict__ feats,
                                                       float* __restrict__ out) {
    __shared__ unsigned short slist[N_GAUSS];
    __shared__ int swarp[9];

    const int tid = threadIdx.x;
    const int tx0 = blockIdx.x * 8;
    const int ty0 = blockIdx.y * 8;
    const int tz0 = blockIdx.z * 8;
    const int lane = tid & 31, wid = tid >> 5;

    // ---- Cull: each thread tests a contiguous chunk of 32 gaussians ----
    const int base = tid * 32;
    int cnt = 0;
    #pragma unroll 8
    for (int k = 0; k < 32; k++) {
        uint2 p = g_aabb[base + k];
        int xmin = p.x & 255, xmax = (p.x >> 8) & 255;
        int ymin = (p.x >> 16) & 255, ymax = (p.x >> 24) & 255;
        int zmin = p.y & 255, zmax = (p.y >> 8) & 255;
        bool hit = (xmin <= tx0 + 7) & (xmax >= tx0) &
                   (ymin <= ty0 + 7) & (ymax >= ty0) &
                   (zmin <= tz0 + 7) & (zmax >= tz0);
        cnt += hit ? 1 : 0;
    }

    int inc = cnt;
    #pragma unroll
    for (int o = 1; o < 32; o <<= 1) {
        int y = __shfl_up_sync(0xffffffffu, inc, o);
        if (lane >= o) inc += y;
    }
    if (lane == 31) swarp[wid] = inc;
    __syncthreads();
    if (tid == 0) {
        int s = 0;
        #pragma unroll
        for (int w2 = 0; w2 < 8; w2++) { int t = swarp[w2]; swarp[w2] = s; s += t; }
        swarp[8] = s;
    }
    __syncthreads();
    int off = swarp[wid] + (inc - cnt);

    #pragma unroll 8
    for (int k = 0; k < 32; k++) {
        uint2 p = g_aabb[base + k];
        int xmin = p.x & 255, xmax = (p.x >> 8) & 255;
        int ymin = (p.x >> 16) & 255, ymax = (p.x >> 24) & 255;
        int zmin = p.y & 255, zmax = (p.y >> 8) & 255;
        bool hit = (xmin <= tx0 + 7) & (xmax >= tx0) &
                   (ymin <= ty0 + 7) & (ymax >= ty0) &
                   (zmin <= tz0 + 7) & (zmax >= tz0);
        if (hit) slist[off++] = (unsigned short)(base + k);
    }
    __syncthreads();
    const int nsurv = swarp[8];

    // ---- Evaluate: two z-adjacent voxels per thread ----
    // Warp-cube mapping: warp (wx,wy,wz) covers a 4x4x4 voxel cube of the tile.
    const int wx = wid >> 2, wy = (wid >> 1) & 1, wz = wid & 1;
    const int ix = wx * 4 + (lane >> 3);
    const int iy = wy * 4 + ((lane >> 1) & 3);
    const int izh = wz * 4 + (lane & 1) * 2;
    const float cx  = ((float)(tx0 + ix) + 0.5f) * VOX + VMINX;
    const float cy  = ((float)(ty0 + iy) + 0.5f) * VOX + VMINY;
    const float cz0 = ((float)(tz0 + izh) + 0.5f) * VOX + VMINZ;
    const float cz1 = ((float)(tz0 + izh + 1) + 0.5f) * VOX + VMINZ;

    float acc0[32], acc1[32];
    #pragma unroll
    for (int k = 0; k < 32; k++) { acc0[k] = 0.f; acc1[k] = 0.f; }

    // Software-pipelined prefetch of next gaussian's header data.
    int gi = (nsurv > 0) ? slist[0] : 0;
    float4 pf0 = g_prec[4*gi + 0];
    float4 pf1 = g_prec[4*gi + 1];

    for (int j = 0; j < nsurv; j++) {
        const int gcur = gi;
        const float4 f0 = pf0;
        const float4 f1 = pf1;
        // prefetch j+1 (clamped; redundant load on last iter is harmless)
        {
            int jn = (j + 1 < nsurv) ? (j + 1) : j;
            int gn = slist[jn];
            pf0 = g_prec[4*gn + 0];
            pf1 = g_prec[4*gn + 1];
            gi = gn;
        }

        float dx = cx - f0.x, dy = cy - f0.y;
        float dz0 = cz0 - f0.z, dz1 = cz1 - f0.z;
        bool mxy = (fabsf(dx) <= f1.x) & (fabsf(dy) <= f1.y);
        bool m0 = mxy & (fabsf(dz0) <= f1.z);
        bool m1 = mxy & (fabsf(dz1) <= f1.z);
        if (__ballot_sync(0xffffffffu, m0 | m1)) {
            float wgt0 = 0.f, wgt1 = 0.f;
            if (m0 | m1) {
                float4 f2 = g_prec[4*gcur + 2];
                float4 f3 = g_prec[4*gcur + 3];
                float txy = f1.w * dx * dx + f2.x * dy * dy + 2.f * f2.z * dx * dy;
                float u   = f2.w * dx + f3.x * dy;           // c02*dx + c12*dy
                if (m0) {
                    float maha0 = txy + f2.y * dz0 * dz0 + 2.f * dz0 * u;
                    wgt0 = f0.w * __expf(-0.5f * maha0);
                }
                if (m1) {
                    float maha1 = txy + f2.y * dz1 * dz1 + 2.f * dz1 * u;
                    wgt1 = f0.w * __expf(-0.5f * maha1);
                }
            }
            const float4* fp = (const float4*)(feats + (size_t)gcur * 32);
            #pragma unroll
            for (int k = 0; k < 8; k++) {
                float4 f = __ldg(fp + k);
                acc0[4*k+0] += wgt0 * f.x;
                acc0[4*k+1] += wgt0 * f.y;
                acc0[4*k+2] += wgt0 * f.z;
                acc0[4*k+3] += wgt0 * f.w;
                acc1[4*k+0] += wgt1 * f.x;
                acc1[4*k+1] += wgt1 * f.y;
                acc1[4*k+2] += wgt1 * f.z;
                acc1[4*k+3] += wgt1 * f.w;
            }
        }
    }

    size_t o = ((((size_t)(tx0 + ix)) * GW + (size_t)(ty0 + iy)) * GD + (size_t)(tz0 + izh)) * 32;
    float4* op = (float4*)(out + o);
    #pragma unroll
    for (int k = 0; k < 8; k++)
        op[k] = make_float4(acc0[4*k+0], acc0[4*k+1], acc0[4*k+2], acc0[4*k+3]);
    #pragma unroll
    for (int k = 0; k < 8; k++)
        op[8 + k] = make_float4(acc1[4*k+0], acc1[4*k+1], acc1[4*k+2], acc1[4*k+3]);
}

extern "C" void kernel_launch(void* const* d_in, const int* in_sizes, int n_in,
                              void* d_out, int out_size) {
    const float* means  = (const float*)d_in[0];
    const float* opac   = (const float*)d_in[1];
    const float* scales = (const float*)d_in[2];
    const float* rots   = (const float*)d_in[3];
    const float* feats  = (const float*)d_in[4];
    float* out = (float*)d_out;

    precompute_kernel<<<(N_GAUSS + 255) / 256, 256>>>(means, opac, scales, rots);
    splat_kernel<<<dim3(GH / 8, GW / 8, GD / 8), 256>>>(feats, out);
}

// round 7
// speedup vs baseline: 1.6570x; 1.0855x over previous
#include <cuda_runtime.h>
#include <cstdint>

#define N_GAUSS 8192
#define GH 160
#define GW 160
#define GD 16
#define VOX 0.4f
#define VMINX (-32.0f)
#define VMINY (-32.0f)
#define VMINZ (-1.0f)
#define WCAP 1024

__device__ float4 g_prec[N_GAUSS * 4];
// Packed integer voxel AABB: x = xmin|xmax<<8|ymin<<16|ymax<<24, y = zmin|zmax<<8
__device__ uint2 g_aabb[N_GAUSS];

__global__ void precompute_kernel(const float* __restrict__ means,
                                  const float* __restrict__ opac,
                                  const float* __restrict__ scales,
                                  const float* __restrict__ rots) {
    int i = blockIdx.x * blockDim.x + threadIdx.x;
    if (i >= N_GAUSS) return;

    float qw = rots[4*i+0], qx = rots[4*i+1], qy = rots[4*i+2], qz = rots[4*i+3];
    float invn = rsqrtf(qw*qw + qx*qx + qy*qy + qz*qz);
    qw *= invn; qx *= invn; qy *= invn; qz *= invn;

    float r00 = 1.f - 2.f*(qy*qy + qz*qz), r01 = 2.f*(qx*qy - qw*qz), r02 = 2.f*(qx*qz + qw*qy);
    float r10 = 2.f*(qx*qy + qw*qz), r11 = 1.f - 2.f*(qx*qx + qz*qz), r12 = 2.f*(qy*qz - qw*qx);
    float r20 = 2.f*(qx*qz - qw*qy), r21 = 2.f*(qy*qz + qw*qx), r22 = 1.f - 2.f*(qx*qx + qy*qy);

    float sx = scales[3*i+0], sy = scales[3*i+1], sz = scales[3*i+2];
    float ax = sx*sx, ay = sy*sy, az = sz*sz;
    float vx = 1.f/ax, vy = 1.f/ay, vz = 1.f/az;

    float s3x = 3.f * sqrtf(r00*r00*ax + r01*r01*ay + r02*r02*az);
    float s3y = 3.f * sqrtf(r10*r10*ax + r11*r11*ay + r12*r12*az);
    float s3z = 3.f * sqrtf(r20*r20*ax + r21*r21*ay + r22*r22*az);

    float c00 = r00*r00*vx + r01*r01*vy + r02*r02*vz;
    float c11 = r10*r10*vx + r11*r11*vy + r12*r12*vz;
    float c22 = r20*r20*vx + r21*r21*vy + r22*r22*vz;
    float c01 = r00*r10*vx + r01*r11*vy + r02*r12*vz;
    float c02 = r00*r20*vx + r01*r21*vy + r02*r22*vz;
    float c12 = r10*r20*vx + r11*r21*vy + r12*r22*vz;

    float mx = means[3*i+0], my = means[3*i+1], mz = means[3*i+2];

    g_prec[4*i+0] = make_float4(mx, my, mz, opac[i]);
    g_prec[4*i+1] = make_float4(s3x, s3y, s3z, c00);
    g_prec[4*i+2] = make_float4(c11, c22, c01, c02);
    g_prec[4*i+3] = make_float4(c12, 0.f, 0.f, 0.f);

    // Conservative integer voxel AABB (widened by 1 voxel each side).
    int x0 = (int)floorf((mx - s3x - VMINX) * 2.5f - 0.5f) - 1;
    int x1 = (int)floorf((mx + s3x - VMINX) * 2.5f - 0.5f) + 2;
    int y0 = (int)floorf((my - s3y - VMINY) * 2.5f - 0.5f) - 1;
    int y1 = (int)floorf((my + s3y - VMINY) * 2.5f - 0.5f) + 2;
    int z0 = (int)floorf((mz - s3z - VMINZ) * 2.5f - 0.5f) - 1;
    int z1 = (int)floorf((mz + s3z - VMINZ) * 2.5f - 0.5f) + 2;
    x0 = min(max(x0, 0), GH - 1); x1 = min(max(x1, 0), GH - 1);
    y0 = min(max(y0, 0), GW - 1); y1 = min(max(y1, 0), GW - 1);
    z0 = min(max(z0, 0), GD - 1); z1 = min(max(z1, 0), GD - 1);

    uint2 p;
    p.x = (unsigned)x0 | ((unsigned)x1 << 8) | ((unsigned)y0 << 16) | ((unsigned)y1 << 24);
    p.y = (unsigned)z0 | ((unsigned)z1 << 8);
    g_aabb[i] = p;
}

// Tile = 8x8x8 voxels, 256 threads, 2 z-adjacent voxels per thread.
// Level 1: block cull (8192 -> slist). Level 2: per-warp cull against the
// warp's 4x4x4 cube (slist -> wlist). Eval loop over wlist is branch-free.
__global__ void __launch_bounds__(256, 2) splat_kernel(const float* __restrict__ feats,
                                                       float* __restrict__ out) {
    __shared__ unsigned short slist[N_GAUSS];
    __shared__ unsigned short wlist[8][WCAP];
    __shared__ int swarp[9];

    const int tid = threadIdx.x;
    const int tx0 = blockIdx.x * 8;
    const int ty0 = blockIdx.y * 8;
    const int tz0 = blockIdx.z * 8;
    const int lane = tid & 31, wid = tid >> 5;

    // ---- Level 1 cull ----
    const int base = tid * 32;
    int cnt = 0;
    #pragma unroll 8
    for (int k = 0; k < 32; k++) {
        uint2 p = g_aabb[base + k];
        int xmin = p.x & 255, xmax = (p.x >> 8) & 255;
        int ymin = (p.x >> 16) & 255, ymax = (p.x >> 24) & 255;
        int zmin = p.y & 255, zmax = (p.y >> 8) & 255;
        bool hit = (xmin <= tx0 + 7) & (xmax >= tx0) &
                   (ymin <= ty0 + 7) & (ymax >= ty0) &
                   (zmin <= tz0 + 7) & (zmax >= tz0);
        cnt += hit ? 1 : 0;
    }

    int inc = cnt;
    #pragma unroll
    for (int o = 1; o < 32; o <<= 1) {
        int y = __shfl_up_sync(0xffffffffu, inc, o);
        if (lane >= o) inc += y;
    }
    if (lane == 31) swarp[wid] = inc;
    __syncthreads();
    if (tid == 0) {
        int s = 0;
        #pragma unroll
        for (int w2 = 0; w2 < 8; w2++) { int t = swarp[w2]; swarp[w2] = s; s += t; }
        swarp[8] = s;
    }
    __syncthreads();
    int off = swarp[wid] + (inc - cnt);

    #pragma unroll 8
    for (int k = 0; k < 32; k++) {
        uint2 p = g_aabb[base + k];
        int xmin = p.x & 255, xmax = (p.x >> 8) & 255;
        int ymin = (p.x >> 16) & 255, ymax = (p.x >> 24) & 255;
        int zmin = p.y & 255, zmax = (p.y >> 8) & 255;
        bool hit = (xmin <= tx0 + 7) & (xmax >= tx0) &
                   (ymin <= ty0 + 7) & (ymax >= ty0) &
                   (zmin <= tz0 + 7) & (zmax >= tz0);
        if (hit) slist[off++] = (unsigned short)(base + k);
    }
    __syncthreads();
    const int nsurv = swarp[8];

    // ---- Warp-cube geometry ----
    const int wx = wid >> 2, wy = (wid >> 1) & 1, wz = wid & 1;
    const int wx0 = tx0 + wx * 4, wy0 = ty0 + wy * 4, wz0 = tz0 + wz * 4;
    const int ix = wx0 + (lane >> 3);
    const int iy = wy0 + ((lane >> 1) & 3);
    const int izh = wz0 + (lane & 1) * 2;
    const float cx  = ((float)ix + 0.5f) * VOX + VMINX;
    const float cy  = ((float)iy + 0.5f) * VOX + VMINY;
    const float cz0 = ((float)izh + 0.5f) * VOX + VMINZ;
    const float cz1 = ((float)(izh + 1) + 0.5f) * VOX + VMINZ;

    float acc0[32], acc1[32];
    #pragma unroll
    for (int k = 0; k < 32; k++) { acc0[k] = 0.f; acc1[k] = 0.f; }

    const bool useWarpList = (nsurv <= WCAP);

    if (useWarpList) {
        // ---- Level 2 cull: warp re-culls slist against its 4x4x4 cube ----
        int wcnt = 0;
        for (int b = 0; b < nsurv; b += 32) {
            int j = b + lane;
            bool hit = false;
            int g = 0;
            if (j < nsurv) {
                g = slist[j];
                uint2 p = g_aabb[g];
                int xmin = p.x & 255, xmax = (p.x >> 8) & 255;
                int ymin = (p.x >> 16) & 255, ymax = (p.x >> 24) & 255;
                int zmin = p.y & 255, zmax = (p.y >> 8) & 255;
                hit = (xmin <= wx0 + 3) & (xmax >= wx0) &
                      (ymin <= wy0 + 3) & (ymax >= wy0) &
                      (zmin <= wz0 + 3) & (zmax >= wz0);
            }
            unsigned mask = __ballot_sync(0xffffffffu, hit);
            if (hit) wlist[wid][wcnt + __popc(mask & ((1u << lane) - 1u))] = (unsigned short)g;
            wcnt += __popc(mask);
        }
        __syncwarp();

        // ---- Dense branch-free eval over the warp list ----
        int gi = (wcnt > 0) ? wlist[wid][0] : 0;
        float4 pf0 = g_prec[4*gi + 0];
        float4 pf1 = g_prec[4*gi + 1];

        for (int j = 0; j < wcnt; j++) {
            const int gcur = gi;
            const float4 f0 = pf0;
            const float4 f1 = pf1;
            {
                int jn = (j + 1 < wcnt) ? (j + 1) : j;
                int gn = wlist[wid][jn];
                pf0 = g_prec[4*gn + 0];
                pf1 = g_prec[4*gn + 1];
                gi = gn;
            }
            float4 f2 = g_prec[4*gcur + 2];
            float4 f3 = g_prec[4*gcur + 3];

            float dx = cx - f0.x, dy = cy - f0.y;
            float dz0 = cz0 - f0.z, dz1 = cz1 - f0.z;
            bool mxy = (fabsf(dx) <= f1.x) & (fabsf(dy) <= f1.y);
            bool m0 = mxy & (fabsf(dz0) <= f1.z);
            bool m1 = mxy & (fabsf(dz1) <= f1.z);

            float txy = f1.w * dx * dx + f2.x * dy * dy + 2.f * f2.z * dx * dy;
            float u   = f2.w * dx + f3.x * dy;
            float e0 = __expf(-0.5f * (txy + f2.y * dz0 * dz0 + 2.f * dz0 * u));
            float e1 = __expf(-0.5f * (txy + f2.y * dz1 * dz1 + 2.f * dz1 * u));
            float wgt0 = m0 ? f0.w * e0 : 0.f;
            float wgt1 = m1 ? f0.w * e1 : 0.f;

            const float4* fp = (const float4*)(feats + (size_t)gcur * 32);
            #pragma unroll
            for (int k = 0; k < 8; k++) {
                float4 f = __ldg(fp + k);
                acc0[4*k+0] += wgt0 * f.x;
                acc0[4*k+1] += wgt0 * f.y;
                acc0[4*k+2] += wgt0 * f.z;
                acc0[4*k+3] += wgt0 * f.w;
                acc1[4*k+0] += wgt1 * f.x;
                acc1[4*k+1] += wgt1 * f.y;
                acc1[4*k+2] += wgt1 * f.z;
                acc1[4*k+3] += wgt1 * f.w;
            }
        }
    } else {
        // ---- Fallback (nsurv > WCAP): ballot-guarded loop over slist ----
        int gi = (nsurv > 0) ? slist[0] : 0;
        float4 pf0 = g_prec[4*gi + 0];
        float4 pf1 = g_prec[4*gi + 1];

        for (int j = 0; j < nsurv; j++) {
            const int gcur = gi;
            const float4 f0 = pf0;
            const float4 f1 = pf1;
            {
                int jn = (j + 1 < nsurv) ? (j + 1) : j;
                int gn = slist[jn];
                pf0 = g_prec[4*gn + 0];
                pf1 = g_prec[4*gn + 1];
                gi = gn;
            }
            float dx = cx - f0.x, dy = cy - f0.y;
            float dz0 = cz0 - f0.z, dz1 = cz1 - f0.z;
            bool mxy = (fabsf(dx) <= f1.x) & (fabsf(dy) <= f1.y);
            bool m0 = mxy & (fabsf(dz0) <= f1.z);
            bool m1 = mxy & (fabsf(dz1) <= f1.z);
            if (__ballot_sync(0xffffffffu, m0 | m1)) {
                float wgt0 = 0.f, wgt1 = 0.f;
                if (m0 | m1) {
                    float4 f2 = g_prec[4*gcur + 2];
                    float4 f3 = g_prec[4*gcur + 3];
                    float txy = f1.w * dx * dx + f2.x * dy * dy + 2.f * f2.z * dx * dy;
                    float u   = f2.w * dx + f3.x * dy;
                    if (m0) wgt0 = f0.w * __expf(-0.5f * (txy + f2.y * dz0 * dz0 + 2.f * dz0 * u));
                    if (m1) wgt1 = f0.w * __expf(-0.5f * (txy + f2.y * dz1 * dz1 + 2.f * dz1 * u));
                }
                const float4* fp = (const float4*)(feats + (size_t)gcur * 32);
                #pragma unroll
                for (int k = 0; k < 8; k++) {
                    float4 f = __ldg(fp + k);
                    acc0[4*k+0] += wgt0 * f.x;
                    acc0[4*k+1] += wgt0 * f.y;
                    acc0[4*k+2] += wgt0 * f.z;
                    acc0[4*k+3] += wgt0 * f.w;
                    acc1[4*k+0] += wgt1 * f.x;
                    acc1[4*k+1] += wgt1 * f.y;
                    acc1[4*k+2] += wgt1 * f.z;
                    acc1[4*k+3] += wgt1 * f.w;
                }
            }
        }
    }

    size_t o = ((((size_t)ix) * GW + (size_t)iy) * GD + (size_t)izh) * 32;
    float4* op = (float4*)(out + o);
    #pragma unroll
    for (int k = 0; k < 8; k++)
        op[k] = make_float4(acc0[4*k+0], acc0[4*k+1], acc0[4*k+2], acc0[4*k+3]);
    #pragma unroll
    for (int k = 0; k < 8; k++)
        op[8 + k] = make_float4(acc1[4*k+0], acc1[4*k+1], acc1[4*k+2], acc1[4*k+3]);
}

extern "C" void kernel_launch(void* const* d_in, const int* in_sizes, int n_in,
                              void* d_out, int out_size) {
    const float* means  = (const float*)d_in[0];
    const float* opac   = (const float*)d_in[1];
    const float* scales = (const float*)d_in[2];
    const float* rots   = (const float*)d_in[3];
    const float* feats  = (const float*)d_in[4];
    float* out = (float*)d_out;

    precompute_kernel<<<(N_GAUSS + 255) / 256, 256>>>(means, opac, scales, rots);
    splat_kernel<<<dim3(GH / 8, GW / 8, GD / 8), 256>>>(feats, out);
}